// round 1
// baseline (speedup 1.0000x reference)
#include <cuda_runtime.h>
#include <cstdint>

// H100SmartEmbedding: out[r, :] = concat(price[0], size[0], exch[r%3], pair[r%7],
//                                        level[r%15], time[r%31]), each 128 fp32.
// Pure HBM-write-bound broadcast. One warp per 128-float section; float4 stores.

__global__ void __launch_bounds__(192)
smart_embedding_kernel(const float4* __restrict__ price,
                       const float4* __restrict__ size_,
                       const float4* __restrict__ exch,
                       const float4* __restrict__ pair,
                       const float4* __restrict__ level,
                       const float4* __restrict__ timew,
                       float4* __restrict__ out,
                       int num_features)
{
    const int t   = threadIdx.x;   // 0..191
    const int sec = t >> 5;        // warp id = section id
    const int c4  = t & 31;        // float4 column within the 128-float section

    // Sections 0/1 are row-invariant: hoist the load out of the loop.
    float4 const_v;
    if (sec == 0)      const_v = __ldg(&price[c4]);
    else if (sec == 1) const_v = __ldg(&size_[c4]);

    const int stride = gridDim.x;

    #pragma unroll 4
    for (int r = blockIdx.x; r < num_features; r += stride) {
        float4 v;
        if (sec == 0) {
            v = const_v;
        } else if (sec == 1) {
            v = const_v;
        } else if (sec == 2) {
            int tr = r % 3;                      // compile-time const mod -> mul/shift
            v = __ldg(&exch[tr * 32 + c4]);
        } else if (sec == 3) {
            int tr = r % 7;
            v = __ldg(&pair[tr * 32 + c4]);
        } else if (sec == 4) {
            int tr = r % 15;
            v = __ldg(&level[tr * 32 + c4]);
        } else {
            int tr = r % 31;
            v = __ldg(&timew[tr * 32 + c4]);
        }
        // Row r spans 192 float4s; thread t writes float4 #t of the row.
        out[(size_t)r * 192 + t] = v;
    }
}

extern "C" void kernel_launch(void* const* d_in, const int* in_sizes, int n_in,
                              void* d_out, int out_size)
{
    const float4* price = (const float4*)d_in[0];
    const float4* size_ = (const float4*)d_in[1];
    const float4* exch  = (const float4*)d_in[2];
    const float4* pair  = (const float4*)d_in[3];
    const float4* level = (const float4*)d_in[4];
    const float4* timew = (const float4*)d_in[5];
    float4* out = (float4*)d_out;

    // num_features lives in device memory (d_in[6]); reading it would need a
    // sync copy (forbidden under graph capture). Derive it from out_size.
    const int num_features = out_size / 768;

    // ~10 blocks/SM x 148 SMs, 6 warps/block -> ~60 warps/SM.
    int grid = 1480;
    if (grid > num_features) grid = num_features;

    smart_embedding_kernel<<<grid, 192>>>(price, size_, exch, pair, level, timew,
                                          out, num_features);
}

// round 2
// speedup vs baseline: 1.1002x; 1.1002x over previous
#include <cuda_runtime.h>
#include <cstdint>

// H100SmartEmbedding: out[r, :] = concat(price[0], size[0], exch[r%3], pair[r%7],
//                                        level[r%15], time[r%31]), 6 x 128 fp32.
//
// Period trick: lcm(3,7,15,31) = 3255. Launch grid = 3255 with stride 3255:
// every row a block touches has the SAME (r%3, r%7, r%15, r%31). Each warp
// loads its table float4 once; the mainloop is a pure STG.128 stream.

#define PERIOD 3255

__global__ void __launch_bounds__(192)
smart_embedding_kernel(const float4* __restrict__ price,
                       const float4* __restrict__ size_,
                       const float4* __restrict__ exch,
                       const float4* __restrict__ pair,
                       const float4* __restrict__ level,
                       const float4* __restrict__ timew,
                       float4* __restrict__ out,
                       int num_features)
{
    const int t   = threadIdx.x;   // 0..191
    const int sec = t >> 5;        // warp id = section id
    const int c4  = t & 31;        // float4 column within the 128-float section
    const int bid = blockIdx.x;

    if (bid >= num_features) return;

    // Block-constant table row per section (r ≡ bid mod {3,7,15,31} for all r
    // this block writes). One LDG per thread for the whole kernel.
    float4 v;
    if (sec == 0) {
        v = __ldg(&price[c4]);
    } else if (sec == 1) {
        v = __ldg(&size_[c4]);
    } else if (sec == 2) {
        v = __ldg(&exch[(bid % 3) * 32 + c4]);
    } else if (sec == 3) {
        v = __ldg(&pair[(bid % 7) * 32 + c4]);
    } else if (sec == 4) {
        v = __ldg(&level[(bid % 15) * 32 + c4]);
    } else {
        v = __ldg(&timew[(bid % 31) * 32 + c4]);
    }

    // Pure store stream: row r spans 192 float4s, thread t writes float4 #t.
    // Streaming hint (.cs): write-once data, evict-first in L2.
    float4* p = out + (size_t)bid * 192 + t;
    const size_t step = (size_t)PERIOD * 192;

    int r = bid;
    #pragma unroll 4
    for (; r + 3 * PERIOD < num_features; r += 4 * PERIOD) {
        __stcs(p, v);
        __stcs(p + step, v);
        __stcs(p + 2 * step, v);
        __stcs(p + 3 * step, v);
        p += 4 * step;
    }
    for (; r < num_features; r += PERIOD) {
        __stcs(p, v);
        p += step;
    }
}

extern "C" void kernel_launch(void* const* d_in, const int* in_sizes, int n_in,
                              void* d_out, int out_size)
{
    const float4* price = (const float4*)d_in[0];
    const float4* size_ = (const float4*)d_in[1];
    const float4* exch  = (const float4*)d_in[2];
    const float4* pair  = (const float4*)d_in[3];
    const float4* level = (const float4*)d_in[4];
    const float4* timew = (const float4*)d_in[5];
    float4* out = (float4*)d_out;

    // num_features lives in device memory (d_in[6]); deriving it host-side
    // from out_size keeps kernel_launch graph-capturable.
    const int num_features = out_size / 768;

    // grid MUST be PERIOD so each block's residues mod 3/7/15/31 are constant.
    smart_embedding_kernel<<<PERIOD, 192>>>(price, size_, exch, pair, level, timew,
                                            out, num_features);
}

// round 3
// speedup vs baseline: 1.1769x; 1.0698x over previous
#include <cuda_runtime.h>
#include <cstdint>

// H100SmartEmbedding: out[r, :] = concat(price[0], size[0], exch[r%3], pair[r%7],
//                                        level[r%15], time[r%31]), 6 x 128 fp32.
//
// Period trick: lcm(3,7,15,31) = 3255. Any stride that's a multiple of 3255
// preserves all four residues, so each block sees ONE set of table rows:
// one LDG per thread for the whole kernel, then a pure STG.128 stream.
//
// R3: split each residue class across SPLIT=3 blocks (grid = 9765, ~13 rows
// per block) to shrink the final-wave drain tail that capped DRAM% at 68.

#define PERIOD 3255
#define SPLIT  3

__global__ void __launch_bounds__(192)
smart_embedding_kernel(const float4* __restrict__ price,
                       const float4* __restrict__ size_,
                       const float4* __restrict__ exch,
                       const float4* __restrict__ pair,
                       const float4* __restrict__ level,
                       const float4* __restrict__ timew,
                       float4* __restrict__ out,
                       int num_features)
{
    const int t   = threadIdx.x;   // 0..191
    const int sec = t >> 5;        // warp id = section id
    const int c4  = t & 31;        // float4 column within the 128-float section

    const int residue = blockIdx.x % PERIOD;  // const-mod -> mul/shift, once/block
    const int chunk   = blockIdx.x / PERIOD;  // 0..SPLIT-1

    // Block-constant table row per section: every row this block writes is
    // ≡ residue (mod 3255), hence fixed residues mod 3/7/15/31.
    float4 v;
    if (sec == 0) {
        v = __ldg(&price[c4]);
    } else if (sec == 1) {
        v = __ldg(&size_[c4]);
    } else if (sec == 2) {
        v = __ldg(&exch[(residue % 3) * 32 + c4]);
    } else if (sec == 3) {
        v = __ldg(&pair[(residue % 7) * 32 + c4]);
    } else if (sec == 4) {
        v = __ldg(&level[(residue % 15) * 32 + c4]);
    } else {
        v = __ldg(&timew[(residue % 31) * 32 + c4]);
    }

    // Rows handled by this block: residue + chunk*PERIOD, stepping SPLIT*PERIOD.
    int r = residue + chunk * PERIOD;
    if (r >= num_features) return;

    const int    rstride = SPLIT * PERIOD;
    const size_t step    = (size_t)rstride * 192;
    float4* p = out + (size_t)r * 192 + t;

    // Pure store stream; .cs = evict-first for write-once data.
    #pragma unroll 4
    for (; r + 3 * rstride < num_features; r += 4 * rstride) {
        __stcs(p, v);
        __stcs(p + step, v);
        __stcs(p + 2 * step, v);
        __stcs(p + 3 * step, v);
        p += 4 * step;
    }
    for (; r < num_features; r += rstride) {
        __stcs(p, v);
        p += step;
    }
}

extern "C" void kernel_launch(void* const* d_in, const int* in_sizes, int n_in,
                              void* d_out, int out_size)
{
    const float4* price = (const float4*)d_in[0];
    const float4* size_ = (const float4*)d_in[1];
    const float4* exch  = (const float4*)d_in[2];
    const float4* pair  = (const float4*)d_in[3];
    const float4* level = (const float4*)d_in[4];
    const float4* timew = (const float4*)d_in[5];
    float4* out = (float4*)d_out;

    // num_features lives in device memory (d_in[6]); deriving it host-side
    // from out_size keeps kernel_launch graph-capturable.
    const int num_features = out_size / 768;

    smart_embedding_kernel<<<PERIOD * SPLIT, 192>>>(price, size_, exch, pair,
                                                    level, timew, out,
                                                    num_features);
}

// round 4
// speedup vs baseline: 1.1977x; 1.0176x over previous
#include <cuda_runtime.h>
#include <cstdint>

// H100SmartEmbedding: out[r, :] = concat(price[0], size[0], exch[r%3], pair[r%7],
//                                        level[r%15], time[r%31]), 6 x 128 fp32.
//
// Period trick: lcm(3,7,15,31) = 3255. Any row stride that's a multiple of
// 3255 preserves all four residues, so each block sees ONE set of table rows:
// one LDG per thread for the whole kernel, then a pure STG.128 stream.
//
// R4: SPLIT 3 -> 6 (grid 19530, ~6.7 rows/block, 13.2 waves of 1480 resident
// blocks). Final-wave drain shrinks from ~0.9 wave-equivalent of idle slots
// to ~0.2, feeding DRAM through the tail.

#define PERIOD 3255
#define SPLIT  6

__global__ void __launch_bounds__(192)
smart_embedding_kernel(const float4* __restrict__ price,
                       const float4* __restrict__ size_,
                       const float4* __restrict__ exch,
                       const float4* __restrict__ pair,
                       const float4* __restrict__ level,
                       const float4* __restrict__ timew,
                       float4* __restrict__ out,
                       int num_features)
{
    const int t   = threadIdx.x;   // 0..191
    const int sec = t >> 5;        // warp id = section id
    const int c4  = t & 31;        // float4 column within the 128-float section

    const int residue = blockIdx.x % PERIOD;  // const-mod -> mul/shift, once/block
    const int chunk   = blockIdx.x / PERIOD;  // 0..SPLIT-1

    // Block-constant table row per section: every row this block writes is
    // ≡ residue (mod 3255), hence fixed residues mod 3/7/15/31.
    float4 v;
    if (sec == 0) {
        v = __ldg(&price[c4]);
    } else if (sec == 1) {
        v = __ldg(&size_[c4]);
    } else if (sec == 2) {
        v = __ldg(&exch[(residue % 3) * 32 + c4]);
    } else if (sec == 3) {
        v = __ldg(&pair[(residue % 7) * 32 + c4]);
    } else if (sec == 4) {
        v = __ldg(&level[(residue % 15) * 32 + c4]);
    } else {
        v = __ldg(&timew[(residue % 31) * 32 + c4]);
    }

    // Rows handled by this block: residue + chunk*PERIOD, stepping SPLIT*PERIOD.
    int r = residue + chunk * PERIOD;
    if (r >= num_features) return;

    const int    rstride = SPLIT * PERIOD;
    const size_t step    = (size_t)rstride * 192;
    float4* p = out + (size_t)r * 192 + t;

    // Pure store stream; .cs = evict-first for write-once data.
    #pragma unroll 4
    for (; r + 3 * rstride < num_features; r += 4 * rstride) {
        __stcs(p, v);
        __stcs(p + step, v);
        __stcs(p + 2 * step, v);
        __stcs(p + 3 * step, v);
        p += 4 * step;
    }
    for (; r < num_features; r += rstride) {
        __stcs(p, v);
        p += step;
    }
}

extern "C" void kernel_launch(void* const* d_in, const int* in_sizes, int n_in,
                              void* d_out, int out_size)
{
    const float4* price = (const float4*)d_in[0];
    const float4* size_ = (const float4*)d_in[1];
    const float4* exch  = (const float4*)d_in[2];
    const float4* pair  = (const float4*)d_in[3];
    const float4* level = (const float4*)d_in[4];
    const float4* timew = (const float4*)d_in[5];
    float4* out = (float4*)d_out;

    // num_features lives in device memory (d_in[6]); deriving it host-side
    // from out_size keeps kernel_launch graph-capturable.
    const int num_features = out_size / 768;

    smart_embedding_kernel<<<PERIOD * SPLIT, 192>>>(price, size_, exch, pair,
                                                    level, timew, out,
                                                    num_features);
}

// round 5
// speedup vs baseline: 1.1983x; 1.0006x over previous
#include <cuda_runtime.h>
#include <cstdint>

// H100SmartEmbedding: out[r, :] = concat(price[0], size[0], exch[r%3], pair[r%7],
//                                        level[r%15], time[r%31]), 6 x 128 fp32.
//
// Period trick: lcm(3,7,15,31) = 3255. Work in ROW PAIRS: block handles pairs
// p ≡ residue (mod 3255); rows 2p and 2p+1 then have block-constant residues
// mod 3/7/15/31. 384 threads = 12 warps = 2 rows x 6 sections; each warp loads
// its table float4 ONCE, mainloop is a pure 6KB-contiguous STG.128 stream.
//
// R5: pair-row blocks (halve block count / prologue overhead, double the
// contiguous write span) at the same 60-warps/SM, 13.2-wave geometry as R4.

#define PERIOD 3255
#define SPLITP 3          // splits per residue class (over pairs)

__global__ void __launch_bounds__(384)
smart_embedding_kernel(const float4* __restrict__ price,
                       const float4* __restrict__ size_,
                       const float4* __restrict__ exch,
                       const float4* __restrict__ pair,
                       const float4* __restrict__ level,
                       const float4* __restrict__ timew,
                       float4* __restrict__ out,
                       int num_features)
{
    const int t   = threadIdx.x;          // 0..383
    const int w   = t >> 5;               // warp 0..11
    const int rip = w / 6;                // row-in-pair: 0 or 1
    const int sec = w % 6;                // section id
    const int c4  = t & 31;               // float4 column within section

    const int residue = blockIdx.x % PERIOD;  // pair residue (const mod -> mul/shift)
    const int chunk   = blockIdx.x / PERIOD;  // 0..SPLITP-1

    // Row handled by this warp at pair p: r = 2p + rip, p ≡ residue (mod 3255)
    // -> r ≡ 2*residue + rip (mod 3255): residues mod 3/7/15/31 are constant.
    const int rbase = 2 * residue + rip;

    float4 v;
    if (sec == 0) {
        v = __ldg(&price[c4]);
    } else if (sec == 1) {
        v = __ldg(&size_[c4]);
    } else if (sec == 2) {
        v = __ldg(&exch[(rbase % 3) * 32 + c4]);
    } else if (sec == 3) {
        v = __ldg(&pair[(rbase % 7) * 32 + c4]);
    } else if (sec == 4) {
        v = __ldg(&level[(rbase % 15) * 32 + c4]);
    } else {
        v = __ldg(&timew[(rbase % 31) * 32 + c4]);
    }

    // Pair p writes out[p*384 + t] (thread-linear across the 2-row, 768-float
    // pair). Pairs stride by SPLITP*PERIOD.
    const int num_pairs = num_features >> 1;       // num_features is even
    int p = residue + chunk * PERIOD;
    if (p >= num_pairs) return;

    const int    pstride = SPLITP * PERIOD;
    const size_t step    = (size_t)pstride * 384;
    float4* ptr = out + (size_t)p * 384 + t;

    // Pure store stream; .cs = evict-first for write-once data.
    #pragma unroll 4
    for (; p + 3 * pstride < num_pairs; p += 4 * pstride) {
        __stcs(ptr, v);
        __stcs(ptr + step, v);
        __stcs(ptr + 2 * step, v);
        __stcs(ptr + 3 * step, v);
        ptr += 4 * step;
    }
    for (; p < num_pairs; p += pstride) {
        __stcs(ptr, v);
        ptr += step;
    }
}

// Fallback for odd num_features (not hit for this dataset, kept for safety):
__global__ void __launch_bounds__(192)
smart_embedding_tail(const float4* __restrict__ price,
                     const float4* __restrict__ size_,
                     const float4* __restrict__ exch,
                     const float4* __restrict__ pair,
                     const float4* __restrict__ level,
                     const float4* __restrict__ timew,
                     float4* __restrict__ out,
                     int row)
{
    const int t   = threadIdx.x;
    const int sec = t >> 5;
    const int c4  = t & 31;
    float4 v;
    if (sec == 0)      v = __ldg(&price[c4]);
    else if (sec == 1) v = __ldg(&size_[c4]);
    else if (sec == 2) v = __ldg(&exch[(row % 3) * 32 + c4]);
    else if (sec == 3) v = __ldg(&pair[(row % 7) * 32 + c4]);
    else if (sec == 4) v = __ldg(&level[(row % 15) * 32 + c4]);
    else               v = __ldg(&timew[(row % 31) * 32 + c4]);
    out[(size_t)row * 192 + t] = v;
}

extern "C" void kernel_launch(void* const* d_in, const int* in_sizes, int n_in,
                              void* d_out, int out_size)
{
    const float4* price = (const float4*)d_in[0];
    const float4* size_ = (const float4*)d_in[1];
    const float4* exch  = (const float4*)d_in[2];
    const float4* pair  = (const float4*)d_in[3];
    const float4* level = (const float4*)d_in[4];
    const float4* timew = (const float4*)d_in[5];
    float4* out = (float4*)d_out;

    // num_features lives in device memory (d_in[6]); deriving it host-side
    // from out_size keeps kernel_launch graph-capturable.
    const int num_features = out_size / 768;

    smart_embedding_kernel<<<PERIOD * SPLITP, 384>>>(price, size_, exch, pair,
                                                     level, timew, out,
                                                     num_features);
    if (num_features & 1) {
        smart_embedding_tail<<<1, 192>>>(price, size_, exch, pair, level, timew,
                                         out, num_features - 1);
    }
}